// round 7
// baseline (speedup 1.0000x reference)
#include <cuda_runtime.h>
#include <cstdint>

#define INC   64
#define DDIM  24
#define BATCH 16
#define DSP   (DDIM*DDIM*DDIM)      // 13824
#define NPOS  (BATCH*DSP)           // 221184
#define ODIM  47

// Scratch: B[b][k][z][y][x], k in [0,27)  (~23.9 MB)
__device__ float g_B[(size_t)BATCH * 27 * DSP];

// ---- packed f32x2 helpers ----
__device__ __forceinline__ unsigned long long pack2(float lo, float hi) {
    unsigned long long r;
    asm("mov.b64 %0, {%1, %2};" : "=l"(r) : "f"(lo), "f"(hi));
    return r;
}
__device__ __forceinline__ void unpack2(unsigned long long v, float& lo, float& hi) {
    asm("mov.b64 {%0, %1}, %2;" : "=f"(lo), "=f"(hi) : "l"(v));
}
__device__ __forceinline__ unsigned long long fma2(unsigned long long a,
                                                   unsigned long long b,
                                                   unsigned long long c) {
    unsigned long long d;
    asm("fma.rn.f32x2 %0, %1, %2, %3;" : "=l"(d) : "l"(a), "l"(b), "l"(c));
    return d;
}

// ============================================================
// Pass 1: B[pos][k] = sum_c x[b,c,pos] * W[c,0,k]
// k-split into two 14-tap halves -> 7 u64 accumulators live,
// low register pressure, high occupancy for latency hiding.
// ============================================================
__global__ void __launch_bounds__(256) conv_pass1(const float* __restrict__ x,
                                                  const float* __restrict__ w) {
    // Two half-weight arrays, 16-float rows (64B, 16B-aligned).
    __shared__ __align__(16) float sW0[64 * 16];   // k = 0..13
    __shared__ __align__(16) float sW1[64 * 16];   // k = 14..26 (+pad)
    const int tid = threadIdx.x;
    for (int idx = tid; idx < 64 * 16; idx += 256) {
        int c = idx >> 4, j = idx & 15;
        sW0[idx] = (j < 14) ? w[c * 1728 + j] : 0.0f;
        sW1[idx] = (j < 13) ? w[c * 1728 + 14 + j] : 0.0f;
    }
    __syncthreads();

    const int p  = blockIdx.x * 256 + tid;   // grid = NPOS/256
    const int b  = p / DSP;
    const int sp = p - b * DSP;
    const float* xp = x + (size_t)b * INC * DSP + sp;
    float* Bp = g_B + (size_t)b * 27 * DSP + sp;

    unsigned long long acc[7];

    // ---- half 0: k = 0..13 ----
#pragma unroll
    for (int j = 0; j < 7; j++) acc[j] = 0ull;
#pragma unroll 8
    for (int c = 0; c < INC; c++) {
        const float xv = __ldg(xp + (size_t)c * DSP);
        const unsigned long long x2 = pack2(xv, xv);
        const ulonglong2* wrow = (const ulonglong2*)(&sW0[c * 16]);
        ulonglong2 w01 = wrow[0], w23 = wrow[1], w45 = wrow[2], w67 = wrow[3];
        acc[0] = fma2(x2, w01.x, acc[0]);
        acc[1] = fma2(x2, w01.y, acc[1]);
        acc[2] = fma2(x2, w23.x, acc[2]);
        acc[3] = fma2(x2, w23.y, acc[3]);
        acc[4] = fma2(x2, w45.x, acc[4]);
        acc[5] = fma2(x2, w45.y, acc[5]);
        acc[6] = fma2(x2, w67.x, acc[6]);   // floats 12,13 (FIX: was u64[3] = floats 6,7)
    }
#pragma unroll
    for (int j = 0; j < 7; j++) {
        float lo, hi;
        unpack2(acc[j], lo, hi);
        Bp[(size_t)(2 * j)     * DSP] = lo;
        Bp[(size_t)(2 * j + 1) * DSP] = hi;
    }

    // ---- half 1: k = 14..26 (+pad) ----
#pragma unroll
    for (int j = 0; j < 7; j++) acc[j] = 0ull;
#pragma unroll 8
    for (int c = 0; c < INC; c++) {
        const float xv = __ldg(xp + (size_t)c * DSP);
        const unsigned long long x2 = pack2(xv, xv);
        const ulonglong2* wrow = (const ulonglong2*)(&sW1[c * 16]);
        ulonglong2 w01 = wrow[0], w23 = wrow[1], w45 = wrow[2], w67 = wrow[3];
        acc[0] = fma2(x2, w01.x, acc[0]);
        acc[1] = fma2(x2, w01.y, acc[1]);
        acc[2] = fma2(x2, w23.x, acc[2]);
        acc[3] = fma2(x2, w23.y, acc[3]);
        acc[4] = fma2(x2, w45.x, acc[4]);
        acc[5] = fma2(x2, w45.y, acc[5]);
        acc[6] = fma2(x2, w67.x, acc[6]);   // floats 12,13 of half-1 row = k 26,pad
    }
#pragma unroll
    for (int j = 0; j < 7; j++) {
        float lo, hi;
        unpack2(acc[j], lo, hi);
        const int k0 = 14 + 2 * j;
        Bp[(size_t)k0 * DSP] = lo;
        if (k0 + 1 < 27) Bp[(size_t)(k0 + 1) * DSP] = hi;
    }
}

// ============================================================
// Pass 2: one thread = one 2x2x2 output octet. Per iz-slab,
// batch all 25 loads (MLP=25), then separable parity sums.
// ============================================================
__global__ void __launch_bounds__(128) conv_pass2(const float* __restrict__ bias,
                                                  float* __restrict__ out) {
    int t = blockIdx.x * 128 + threadIdx.x;   // grid = 221184/128 = 1728
    const int qx = t % 24; t /= 24;
    const int qy = t % 24; t /= 24;
    const int qz = t % 24;
    const int b  = t / 24;

    const float* __restrict__ Bb = g_B + (size_t)b * 27 * DSP;

    // per-dim tables: (weight tap, position delta)
    const int wiT[5]   = {2, 0, 1, 2, 0};
    const int dposT[5] = {-1, 0, 0, 0, 1};

    int zoff[5], yoff[5], xoff[5];
    bool zv[5], yv[5], xv[5];
#pragma unroll
    for (int i = 0; i < 5; i++) {
        const int pz = qz + dposT[i];
        zv[i]   = (pz >= 0) && (pz < DDIM);
        zoff[i] = wiT[i] * 9 * DSP + pz * (DDIM * DDIM);
        const int py = qy + dposT[i];
        yv[i]   = (py >= 0) && (py < DDIM);
        yoff[i] = wiT[i] * 3 * DSP + py * DDIM;
        const int px = qx + dposT[i];
        xv[i]   = (px >= 0) && (px < DDIM);
        xoff[i] = wiT[i] * DSP + px;
    }

    float o8[2][2][2];
#pragma unroll
    for (int a = 0; a < 2; a++)
#pragma unroll
        for (int c = 0; c < 2; c++)
#pragma unroll
            for (int d = 0; d < 2; d++) o8[a][c][d] = 0.0f;

#pragma unroll
    for (int iz = 0; iz < 5; iz++) {
        // batch all 25 loads of this slab first (independent -> MLP 25)
        float v[25];
#pragma unroll
        for (int iy = 0; iy < 5; iy++) {
            const bool vzy = zv[iz] && yv[iy];
            const int base = zoff[iz] + yoff[iy];
#pragma unroll
            for (int ix = 0; ix < 5; ix++) {
                v[iy * 5 + ix] = (vzy && xv[ix]) ? __ldg(Bb + base + xoff[ix]) : 0.0f;
            }
        }
        // separable reduction
        float ys[2][2] = {{0.0f, 0.0f}, {0.0f, 0.0f}};
#pragma unroll
        for (int iy = 0; iy < 5; iy++) {
            const float xs0 = v[iy * 5 + 0] + v[iy * 5 + 1] + v[iy * 5 + 2];
            const float xs1 = v[iy * 5 + 2] + v[iy * 5 + 3] + v[iy * 5 + 4];
            if (iy <= 2) { ys[0][0] += xs0; ys[0][1] += xs1; }
            if (iy >= 2) { ys[1][0] += xs0; ys[1][1] += xs1; }
        }
        if (iz <= 2) {
#pragma unroll
            for (int c = 0; c < 2; c++)
#pragma unroll
                for (int d = 0; d < 2; d++) o8[0][c][d] += ys[c][d];
        }
        if (iz >= 2) {
#pragma unroll
            for (int c = 0; c < 2; c++)
#pragma unroll
                for (int d = 0; d < 2; d++) o8[1][c][d] += ys[c][d];
        }
    }

    const float bv = __ldg(bias);
    const int oz0 = 2 * qz, oy0 = 2 * qy, ox0 = 2 * qx;
#pragma unroll
    for (int pz = 0; pz < 2; pz++) {
        if (oz0 + pz >= ODIM) continue;
#pragma unroll
        for (int py = 0; py < 2; py++) {
            if (oy0 + py >= ODIM) continue;
            const long rbase = (((long)b * ODIM + oz0 + pz) * ODIM + oy0 + py) * ODIM;
#pragma unroll
            for (int pw = 0; pw < 2; pw++) {
                if (ox0 + pw >= ODIM) continue;
                out[rbase + ox0 + pw] = (o8[pz][py][pw] + bv) * 64.0f;
            }
        }
    }
}

extern "C" void kernel_launch(void* const* d_in, const int* in_sizes, int n_in,
                              void* d_out, int out_size) {
    const float* x    = (const float*)d_in[0];
    const float* w    = (const float*)d_in[1];
    const float* bias = (const float*)d_in[2];
    float* out = (float*)d_out;

    conv_pass1<<<NPOS / 256, 256>>>(x, w);      // 864 blocks
    conv_pass2<<<NPOS / 128, 128>>>(bias, out); // 1728 blocks
}